// round 8
// baseline (speedup 1.0000x reference)
#include <cuda_runtime.h>

// ParametricInterpolation: out[b,n] = x[b,pos]*(1-k) + x[b,pos-1]*k,
// pos = clip(n - round(curve), 1, 2047), k = curve - round(curve),
// curve = quartic(params[b]/scaler, n).
//
// Numerics (probe V7):
//   p_k = RN(params_k * inv_k), inv_k = RN(1 / fl32(scaler_k))
//         (XLA algsimp: divide-by-constant -> multiply-by-reciprocal)
//   powers per XLA integer_pow: i2 = i*i (exact), i3 = RN(i2*i), i4 = RN(i2*i2)
//   dot: ascending-k fma chain (cuBLAS/Eigen accumulation order):
//        c = RN(p0*i4); c = fma(p1,i3,c); c = fma(p2,i2,c);
//        c = fma(p3,i,c);  c = RN(c + p4)
//   round = half-to-even (rintf); lerp non-contracted:
//        RN( RN(x1*RN(1-k)) + RN(x2*k) )

#define SIG_LEN 2048

__global__ __launch_bounds__(256, 8)
void pik_kernel(const float* __restrict__ x,
                const float* __restrict__ params,
                float* __restrict__ out)
{
    __shared__ float sx[SIG_LEN];
    __shared__ float sp[5];

    const int b   = blockIdx.x;
    const int tid = threadIdx.x;

    // Stage the row: 2048 floats = 512 float4, 256 threads -> 2 each.
    const float4* xin = reinterpret_cast<const float4*>(x + (size_t)b * SIG_LEN);
    float4* srow = reinterpret_cast<float4*>(sx);
    srow[tid]       = xin[tid];
    srow[tid + 256] = xin[tid + 256];

    if (tid < 5) {
        // Correctly-rounded fp32 reciprocals of the fp32 scaler constants:
        // computed as double(1.0)/double(fl32(scaler)) rounded to fp32, which
        // equals IEEE-RN fp32 division — exactly XLA's folded constant.
        const float inv = (tid == 0) ? (float)(1.0 / (double)1e12f) :
                          (tid == 1) ? (float)(1.0 / (double)1e8f)  :
                          (tid == 2) ? (float)(1.0 / (double)1e4f)  :
                          (tid == 3) ? 1.0f :
                                       (float)(1.0 / (double)10.0f);
        sp[tid] = __fmul_rn(params[(size_t)b * 5 + tid], inv);
    }
    __syncthreads();

    const float p0 = sp[0], p1 = sp[1], p2 = sp[2], p3 = sp[3], p4 = sp[4];

    float4* orow = reinterpret_cast<float4*>(out + (size_t)b * SIG_LEN);

    #pragma unroll
    for (int half = 0; half < 2; ++half) {
        const int n0 = half * 1024 + tid * 4;
        float4 res;
        float* r = reinterpret_cast<float*>(&res);

        #pragma unroll
        for (int j = 0; j < 4; ++j) {
            const float fi = (float)(n0 + j);
            // powers (XLA integer_pow square-and-multiply), pinned RN
            const float i2 = __fmul_rn(fi, fi);   // exact
            const float i3 = __fmul_rn(i2, fi);   // one rounding
            const float i4 = __fmul_rn(i2, i2);   // one rounding

            // ascending-k fma chain (acc init 0)
            float c = __fmul_rn(p0, i4);          // == fma(p0, i4, 0)
            c = __fmaf_rn(p1, i3, c);
            c = __fmaf_rn(p2, i2, c);
            c = __fmaf_rn(p3, fi, c);
            c = __fadd_rn(c, p4);                 // == fma(p4, 1, c)

            const float ci = rintf(c);            // round half to even
            const float k  = __fadd_rn(c, -ci);   // exact

            float posf = fi - ci;                 // exact: integer-valued floats
            posf = fminf(fmaxf(posf, 1.0f), (float)(SIG_LEN - 1));
            const int pos = (int)posf;

            const float x1 = sx[pos];
            const float x2 = sx[pos - 1];
            // eager-form lerp, no fma contraction
            const float w1 = __fsub_rn(1.0f, k);
            r[j] = __fadd_rn(__fmul_rn(x1, w1), __fmul_rn(x2, k));
        }
        orow[n0 >> 2] = res;
    }
}

extern "C" void kernel_launch(void* const* d_in, const int* in_sizes, int n_in,
                              void* d_out, int out_size)
{
    const float* x;
    const float* params;
    if (n_in >= 2 && in_sizes[0] < in_sizes[1]) {
        params = (const float*)d_in[0];
        x      = (const float*)d_in[1];
    } else {
        x      = (const float*)d_in[0];
        params = (const float*)d_in[1];
    }
    float* out = (float*)d_out;

    const int batch = 16384;
    pik_kernel<<<batch, 256>>>(x, params, out);
}

// round 9
// speedup vs baseline: 1.0323x; 1.0323x over previous
#include <cuda_runtime.h>

// ParametricInterpolation — numerics FROZEN (bit-exact vs reference, R8):
//   p_k = RN(params_k * RN(1/fl32(scaler_k)))   (XLA divide->recip-mul)
//   i2 = RN(i*i), i3 = RN(i2*i), i4 = RN(i2*i2) (integer_pow sq-and-mul)
//   c  = RN(p0*i4); fma(p1,i3); fma(p2,i2); fma(p3,i); + p4  (ascending fma)
//   ci = rintf(c); k = c - ci; pos = clip(i - ci, 1, 2047)
//   out = RN(RN(x1*RN(1-k)) + RN(x2*k))          (non-contracted lerp)
//
// Perf change vs R8: compute phase is thread-interleaved (n = part*256+tid)
// so warp-lane smem gathers hit consecutive addresses -> conflict-free LDS
// (was stride-4 = 4-way conflict). Stores become scalar but warp-coalesced.

#define SIG_LEN 2048

__global__ __launch_bounds__(256, 8)
void pik_kernel(const float* __restrict__ x,
                const float* __restrict__ params,
                float* __restrict__ out)
{
    __shared__ float sx[SIG_LEN];
    __shared__ float sp[5];

    const int b   = blockIdx.x;
    const int tid = threadIdx.x;

    // Stage the row: 2048 floats = 512 float4, 256 threads -> 2 each.
    const float4* xin = reinterpret_cast<const float4*>(x + (size_t)b * SIG_LEN);
    float4* srow = reinterpret_cast<float4*>(sx);
    srow[tid]       = xin[tid];
    srow[tid + 256] = xin[tid + 256];

    if (tid < 5) {
        // fp32 correctly-rounded reciprocals of fl32(scaler) — XLA's folded consts.
        const float inv = (tid == 0) ? (float)(1.0 / (double)1e12f) :
                          (tid == 1) ? (float)(1.0 / (double)1e8f)  :
                          (tid == 2) ? (float)(1.0 / (double)1e4f)  :
                          (tid == 3) ? 1.0f :
                                       (float)(1.0 / (double)10.0f);
        sp[tid] = __fmul_rn(params[(size_t)b * 5 + tid], inv);
    }
    __syncthreads();

    const float p0 = sp[0], p1 = sp[1], p2 = sp[2], p3 = sp[3], p4 = sp[4];

    float* orow = out + (size_t)b * SIG_LEN;

    #pragma unroll
    for (int part = 0; part < SIG_LEN / 256; ++part) {
        const int n = part * 256 + tid;
        const float fi = (float)n;

        // powers (XLA integer_pow square-and-multiply), pinned RN
        const float i2 = __fmul_rn(fi, fi);   // exact
        const float i3 = __fmul_rn(i2, fi);
        const float i4 = __fmul_rn(i2, i2);

        // ascending-k fma chain
        float c = __fmul_rn(p0, i4);
        c = __fmaf_rn(p1, i3, c);
        c = __fmaf_rn(p2, i2, c);
        c = __fmaf_rn(p3, fi, c);
        c = __fadd_rn(c, p4);

        const float ci = rintf(c);            // round half to even
        const float k  = __fadd_rn(c, -ci);

        float posf = fi - ci;                 // exact: integer-valued floats
        posf = fminf(fmaxf(posf, 1.0f), (float)(SIG_LEN - 1));
        const int pos = (int)posf;

        const float x1 = sx[pos];             // warp-consecutive -> conflict-free
        const float x2 = sx[pos - 1];

        const float w1 = __fsub_rn(1.0f, k);  // non-contracted lerp
        orow[n] = __fadd_rn(__fmul_rn(x1, w1), __fmul_rn(x2, k));
    }
}

extern "C" void kernel_launch(void* const* d_in, const int* in_sizes, int n_in,
                              void* d_out, int out_size)
{
    const float* x;
    const float* params;
    if (n_in >= 2 && in_sizes[0] < in_sizes[1]) {
        params = (const float*)d_in[0];
        x      = (const float*)d_in[1];
    } else {
        x      = (const float*)d_in[0];
        params = (const float*)d_in[1];
    }
    float* out = (float*)d_out;

    const int batch = 16384;
    pik_kernel<<<batch, 256>>>(x, params, out);
}